// round 4
// baseline (speedup 1.0000x reference)
#include <cuda_runtime.h>

#define STRIDE   10
#define NF       128
#define PAIRS    8128      // 128*127/2
#define NTASKS   12        // 16-row blocks x 64-col chunks covering lower triangle
#define THREADS  384       // 12 warps, exactly 1 task each

// task -> (16-row block index, 64-col chunk index)
__constant__ unsigned char c_bi[NTASKS] = {0,1,2,3,4,4,5,5,6,6,7,7};
__constant__ unsigned char c_jc[NTASKS] = {0,0,0,0,0,1,0,1,0,1,0,1};

__global__ __launch_bounds__(THREADS)
void corr_win_kernel(const float* __restrict__ x, float* __restrict__ out)
{
    __shared__ float ms[STRIDE][NF];   // normalized columns: (x-mean)/||x-mean||

    const int w    = blockIdx.x;       // window = b*100 + l
    const int tid  = threadIdx.x;
    const int warp = tid >> 5;
    const int lane = tid & 31;
    const float* __restrict__ xw = x + (size_t)w * (STRIDE * NF);

    // ---- Phase 1: load column, center, scale by 1/||.||, store to smem ---
    if (tid < NF) {
        float v[STRIDE];
        #pragma unroll
        for (int s = 0; s < STRIDE; ++s) v[s] = __ldcs(&xw[s * NF + tid]);
        float sum = 0.f;
        #pragma unroll
        for (int s = 0; s < STRIDE; ++s) sum += v[s];
        const float mean = sum * (1.0f / STRIDE);
        float s2 = 0.f;
        #pragma unroll
        for (int s = 0; s < STRIDE; ++s) {
            v[s] -= mean;
            s2 = fmaf(v[s], v[s], s2);
        }
        const float invn = (s2 > 0.f) ? rsqrtf(s2) : 0.f;  // divide_no_nan
        #pragma unroll
        for (int s = 0; s < STRIDE; ++s) ms[s][tid] = v[s] * invn;
    }
    __syncthreads();

    float* __restrict__ ow = out + (size_t)w * PAIRS;

    // ---- Phase 2: one 16x64 warp tile per warp ---------------------------
    const int i0    = (int)c_bi[warp] * 16;
    const int jbase = (int)c_jc[warp] * 64;
    const int j0    = jbase + lane;        // first j column (coalesced)
    const int j1    = jbase + 32 + lane;   // second j column (coalesced)

    float acc0[16], acc1[16];
    #pragma unroll
    for (int u = 0; u < 16; ++u) { acc0[u] = 0.f; acc1[u] = 0.f; }

    #pragma unroll
    for (int s = 0; s < STRIDE; ++s) {
        // A rows: broadcast loads (all lanes same address)
        const float4 A0 = *(const float4*)&ms[s][i0];
        const float4 A1 = *(const float4*)&ms[s][i0 + 4];
        const float4 A2 = *(const float4*)&ms[s][i0 + 8];
        const float4 A3 = *(const float4*)&ms[s][i0 + 12];
        // B columns: coalesced scalar loads
        const float b0 = ms[s][j0];
        const float b1 = ms[s][j1];

        const float av[16] = {A0.x, A0.y, A0.z, A0.w,
                              A1.x, A1.y, A1.z, A1.w,
                              A2.x, A2.y, A2.z, A2.w,
                              A3.x, A3.y, A3.z, A3.w};
        #pragma unroll
        for (int u = 0; u < 16; ++u) {
            acc0[u] = fmaf(av[u], b0, acc0[u]);
            acc1[u] = fmaf(av[u], b1, acc1[u]);
        }
    }

    // ---- Phase 3: direct coalesced predicated stores ---------------------
    #pragma unroll
    for (int u = 0; u < 16; ++u) {
        const int i    = i0 + u;
        const int base = (i * (i - 1)) / 2;   // strict-lower-tri row base
        if (j0 < i) __stcs(&ow[base + j0], acc0[u]);
        if (j1 < i) __stcs(&ow[base + j1], acc1[u]);
    }
}

extern "C" void kernel_launch(void* const* d_in, const int* in_sizes, int n_in,
                              void* d_out, int out_size)
{
    const float* x = (const float*)d_in[0];
    float* out     = (float*)d_out;
    int n_windows  = in_sizes[0] / (STRIDE * NF);   // 6400
    corr_win_kernel<<<n_windows, THREADS>>>(x, out);
}

// round 5
// speedup vs baseline: 1.0230x; 1.0230x over previous
#include <cuda_runtime.h>

#define STRIDE   10
#define NF       128
#define PAIRS    8128      // 128*127/2
#define NTASKS   12        // 16-row blocks x 64-col chunks covering lower triangle
#define THREADS  384       // 12 warps, exactly 1 task each

// task -> (16-row block index, 64-col chunk index)
__constant__ unsigned char c_bi[NTASKS] = {0,1,2,3,4,4,5,5,6,6,7,7};
__constant__ unsigned char c_jc[NTASKS] = {0,0,0,0,0,1,0,1,0,1,0,1};

__global__ __launch_bounds__(THREADS, 3)   // cap regs at 56 -> 3 CTAs/SM
void corr_win_kernel(const float* __restrict__ x, float* __restrict__ out)
{
    __shared__ float ms[STRIDE][NF];   // normalized columns: (x-mean)/||x-mean||

    const int w    = blockIdx.x;       // window = b*100 + l
    const int tid  = threadIdx.x;
    const int warp = tid >> 5;
    const int lane = tid & 31;
    const float* __restrict__ xw = x + (size_t)w * (STRIDE * NF);

    // ---- Phase 1: load column, center, scale by 1/||.||, store to smem ---
    if (tid < NF) {
        float v[STRIDE];
        #pragma unroll
        for (int s = 0; s < STRIDE; ++s) v[s] = __ldcs(&xw[s * NF + tid]);
        float sum = 0.f;
        #pragma unroll
        for (int s = 0; s < STRIDE; ++s) sum += v[s];
        const float mean = sum * (1.0f / STRIDE);
        float s2 = 0.f;
        #pragma unroll
        for (int s = 0; s < STRIDE; ++s) {
            v[s] -= mean;
            s2 = fmaf(v[s], v[s], s2);
        }
        const float invn = (s2 > 0.f) ? rsqrtf(s2) : 0.f;  // divide_no_nan
        #pragma unroll
        for (int s = 0; s < STRIDE; ++s) ms[s][tid] = v[s] * invn;
    }
    __syncthreads();

    float* __restrict__ ow = out + (size_t)w * PAIRS;

    // ---- Phase 2: one 16x64 warp tile per warp ---------------------------
    const int i0    = (int)c_bi[warp] * 16;
    const int jbase = (int)c_jc[warp] * 64;
    const int j0    = jbase + lane;        // first j column (coalesced)
    const int j1    = jbase + 32 + lane;   // second j column (coalesced)

    float acc0[16], acc1[16];
    #pragma unroll
    for (int u = 0; u < 16; ++u) { acc0[u] = 0.f; acc1[u] = 0.f; }

    #pragma unroll
    for (int s = 0; s < STRIDE; ++s) {
        const float b0 = ms[s][j0];        // coalesced
        const float b1 = ms[s][j1];        // coalesced

        // interleave each A-quad broadcast with its FMA group to keep the
        // live register set small (one float4 stage at a time)
        #pragma unroll
        for (int q = 0; q < 4; ++q) {
            const float4 A = *(const float4*)&ms[s][i0 + 4 * q];
            acc0[4*q+0] = fmaf(A.x, b0, acc0[4*q+0]);
            acc1[4*q+0] = fmaf(A.x, b1, acc1[4*q+0]);
            acc0[4*q+1] = fmaf(A.y, b0, acc0[4*q+1]);
            acc1[4*q+1] = fmaf(A.y, b1, acc1[4*q+1]);
            acc0[4*q+2] = fmaf(A.z, b0, acc0[4*q+2]);
            acc1[4*q+2] = fmaf(A.z, b1, acc1[4*q+2]);
            acc0[4*q+3] = fmaf(A.w, b0, acc0[4*q+3]);
            acc1[4*q+3] = fmaf(A.w, b1, acc1[4*q+3]);
        }
    }

    // ---- Phase 3: direct coalesced predicated stores ---------------------
    #pragma unroll
    for (int u = 0; u < 16; ++u) {
        const int i    = i0 + u;
        const int base = (i * (i - 1)) / 2;   // strict-lower-tri row base
        if (j0 < i) __stcs(&ow[base + j0], acc0[u]);
        if (j1 < i) __stcs(&ow[base + j1], acc1[u]);
    }
}

extern "C" void kernel_launch(void* const* d_in, const int* in_sizes, int n_in,
                              void* d_out, int out_size)
{
    const float* x = (const float*)d_in[0];
    float* out     = (float*)d_out;
    int n_windows  = in_sizes[0] / (STRIDE * NF);   // 6400
    corr_win_kernel<<<n_windows, THREADS>>>(x, out);
}